// round 9
// baseline (speedup 1.0000x reference)
#include <cuda_runtime.h>
#include <math.h>
#include <stdint.h>

// ---------------------------------------------------------------------------
// SSITrimLoss: masked scale/shift-invariant trimmed L1 loss.
// Pipeline (4 launches):
//   1. pack    : moments + compact valid (p,g) pairs into per-block segments
//   2. hist    : res bits from pairs -> store per-segment uint32 + 8192-bin hist
//   3. compact : level-0 selection (scan 8192 bins); sweep resbits: below-bin
//                sum + match count, ONE atomic reserve, gather -> contiguous
//   4. finish  : 19-bit refine (1024+512 bins) over contiguous candidates
// Selection is bit-exact (monotone uint encoding of non-negative floats).
// ---------------------------------------------------------------------------

#define BB     32
#define NMAX   491520
#define TPB    256
#define BLKX   64
#define SEGLEN (NMAX / BLKX)
#define HBINS  8192
#define HSHIFT 19
#define FULLM  0xffffffffu

__device__ __align__(16) float2       g_pair[(size_t)BB * NMAX];
__device__ __align__(16) unsigned int g_resbits[(size_t)BB * NMAX];
__device__ __align__(16) unsigned int g_cand[(size_t)BB * NMAX];
__device__ float              g_part[BB][BLKX][5];
__device__ int                g_segcnt[BB][BLKX];
__device__ unsigned int       g_hcnt[BB][HBINS];
__device__ int                g_k[BB];
__device__ long long          g_rank[BB];
__device__ int                g_sel0[BB];
__device__ double             g_sumbelow[BB];
__device__ long long          g_cntbelow[BB];
__device__ int                g_candcnt[BB];

// ------------------------- warp reduce/scan helpers ------------------------
__device__ __forceinline__ float warp_sum(float v) {
    #pragma unroll
    for (int off = 16; off; off >>= 1) v += __shfl_down_sync(FULLM, v, off);
    return v;
}
__device__ __forceinline__ double warp_sum_d(double v) {
    #pragma unroll
    for (int off = 16; off; off >>= 1) v += __shfl_down_sync(FULLM, v, off);
    return v;
}
__device__ __forceinline__ long long warp_sum_ll(long long v) {
    #pragma unroll
    for (int off = 16; off; off >>= 1) v += __shfl_down_sync(FULLM, v, off);
    return v;
}
__device__ __forceinline__ int warp_sum_i(int v) {
    #pragma unroll
    for (int off = 16; off; off >>= 1) v += __shfl_down_sync(FULLM, v, off);
    return v;
}
__device__ __forceinline__ int warp_scan_incl(int v, int lane) {
    #pragma unroll
    for (int off = 1; off < 32; off <<= 1) {
        int t = __shfl_up_sync(FULLM, v, off);
        if (lane >= off) v += t;
    }
    return v;
}

// alpha/beta/k from per-block partials; deterministic, identical in all blocks.
struct ABK { float a, be; int k; long long r; };
__device__ __forceinline__ void compute_abk(int b, int tid, ABK* s_out) {
    if (tid < 32) {
        double v0 = 0, v1 = 0, v2 = 0, v3 = 0, v4 = 0;
        #pragma unroll
        for (int j = 0; j < BLKX / 32; j++) {
            int idx = tid + j * 32;
            v0 += (double)g_part[b][idx][0];
            v1 += (double)g_part[b][idx][1];
            v2 += (double)g_part[b][idx][2];
            v3 += (double)g_part[b][idx][3];
            v4 += (double)g_part[b][idx][4];
        }
        v0 = warp_sum_d(v0); v1 = warp_sum_d(v1); v2 = warp_sum_d(v2);
        v3 = warp_sum_d(v3); v4 = warp_sum_d(v4);
        if (tid == 0) {
            double n  = v0;
            double ns = n < 1.0 ? 1.0 : n;
            double md = v1 / ns, mz = v2 / ns;
            double var = v3 / ns - md * md;
            double cov = v4 / ns - md * mz;
            double alpha = cov / (var + 1e-6);
            s_out->a  = (float)alpha;
            s_out->be = (float)(mz - alpha * md);
            int k = (int)floorf(0.8f * (float)n);  // reference-matching f32 arith
            s_out->k = k;
            s_out->r = (long long)k - 1;
        }
    }
}

// ------------------------ 1. pack (moments + gather) -----------------------
__global__ __launch_bounds__(TPB) void pack_kernel(
        const float* __restrict__ pred, const float* __restrict__ gt,
        const int* __restrict__ mask, int N, float* __restrict__ out0) {
    int b = blockIdx.y;
    // zero this sample's hist slice (8192/64 = 128 entries per block)
    if (threadIdx.x < 128) g_hcnt[b][(blockIdx.x << 7) + threadIdx.x] = 0u;
    if (blockIdx.x == 0 && threadIdx.x == 0) {
        g_candcnt[b] = 0;
        g_sumbelow[b] = 0.0;
        if (b == 0) *out0 = 0.f;
    }

    int n4 = N >> 2;
    int chunk4 = n4 / BLKX;
    int start = blockIdx.x * chunk4;
    int end   = (blockIdx.x == BLKX - 1) ? n4 : start + chunk4;

    const float4* p4 = reinterpret_cast<const float4*>(pred) + (size_t)b * n4;
    const float4* g4 = reinterpret_cast<const float4*>(gt)   + (size_t)b * n4;
    const int4*   m4 = reinterpret_cast<const int4*>(mask)   + (size_t)b * n4;
    float2* out = g_pair + (size_t)b * NMAX + (size_t)blockIdx.x * SEGLEN;

    __shared__ int s_cnt;
    if (threadIdx.x == 0) s_cnt = 0;
    __syncthreads();

    int lane = threadIdx.x & 31;
    float sn = 0.f, sp = 0.f, sg = 0.f, spp = 0.f, spg = 0.f;

    for (int i = start + threadIdx.x; i < end; i += TPB) {
        float4 p = p4[i]; float4 g = g4[i]; int4 m = m4[i];
        bool v0 = m.x > 0, v1 = m.y > 0, v2 = m.z > 0, v3 = m.w > 0;
        if (v0) { sn += 1.f; sp += p.x; sg += g.x; spp += p.x*p.x; spg += p.x*g.x; }
        if (v1) { sn += 1.f; sp += p.y; sg += g.y; spp += p.y*p.y; spg += p.y*g.y; }
        if (v2) { sn += 1.f; sp += p.z; sg += g.z; spp += p.z*p.z; spg += p.z*g.z; }
        if (v3) { sn += 1.f; sp += p.w; sg += g.w; spp += p.w*p.w; spg += p.w*g.w; }
        int vc = (int)v0 + (int)v1 + (int)v2 + (int)v3;
        int incl = warp_scan_incl(vc, lane);
        int wtotal = __shfl_sync(FULLM, incl, 31);
        int base = 0;
        if (lane == 31 && wtotal) base = atomicAdd(&s_cnt, wtotal);
        base = __shfl_sync(FULLM, base, 31);
        int o = base + incl - vc;
        if (v0) out[o++] = make_float2(p.x, g.x);
        if (v1) out[o++] = make_float2(p.y, g.y);
        if (v2) out[o++] = make_float2(p.z, g.z);
        if (v3) out[o]   = make_float2(p.w, g.w);
    }

    sn = warp_sum(sn); sp = warp_sum(sp); sg = warp_sum(sg);
    spp = warp_sum(spp); spg = warp_sum(spg);
    __shared__ float ws[5][8];
    int w = threadIdx.x >> 5;
    if (lane == 0) { ws[0][w]=sn; ws[1][w]=sp; ws[2][w]=sg; ws[3][w]=spp; ws[4][w]=spg; }
    __syncthreads();
    if (w == 0) {
        float a0 = lane < 8 ? ws[0][lane] : 0.f;
        float a1 = lane < 8 ? ws[1][lane] : 0.f;
        float a2 = lane < 8 ? ws[2][lane] : 0.f;
        float a3 = lane < 8 ? ws[3][lane] : 0.f;
        float a4 = lane < 8 ? ws[4][lane] : 0.f;
        a0 = warp_sum(a0); a1 = warp_sum(a1); a2 = warp_sum(a2);
        a3 = warp_sum(a3); a4 = warp_sum(a4);
        if (lane == 0) {
            g_part[b][blockIdx.x][0] = a0;
            g_part[b][blockIdx.x][1] = a1;
            g_part[b][blockIdx.x][2] = a2;
            g_part[b][blockIdx.x][3] = a3;
            g_part[b][blockIdx.x][4] = a4;
            g_segcnt[b][blockIdx.x] = s_cnt;
        }
    }
}

// ------------------------------ 2. hist ------------------------------------
// Read pairs, compute residual bits, store per-segment uint32, 8192-bin hist.
__global__ __launch_bounds__(TPB) void hist_kernel() {
    int b = blockIdx.y;
    __shared__ ABK s_abk;
    __shared__ unsigned int sh[HBINS];     // 32 KB
    compute_abk(b, threadIdx.x, &s_abk);
    for (int i = threadIdx.x; i < HBINS; i += TPB) sh[i] = 0u;
    __syncthreads();

    int cnt = g_segcnt[b][blockIdx.x];
    const float2* in = g_pair + (size_t)b * NMAX + (size_t)blockIdx.x * SEGLEN;
    unsigned int* rb = g_resbits + (size_t)b * NMAX + (size_t)blockIdx.x * SEGLEN;
    float a = s_abk.a, be = s_abk.be;

    for (int i = threadIdx.x; i < cnt; i += TPB) {
        float2 pg = in[i];
        float r = fabsf(fmaf(a, pg.x, be) - pg.y);
        unsigned bits = __float_as_uint(r);
        rb[i] = bits;
        atomicAdd(&sh[bits >> HSHIFT], 1u);
    }
    __syncthreads();
    for (int i = threadIdx.x; i < HBINS; i += TPB) {
        unsigned c = sh[i];
        if (c) atomicAdd(&g_hcnt[b][i], c);
    }
}

// ------------------------------ 3. compact ---------------------------------
__global__ __launch_bounds__(TPB) void compact_kernel() {
    int b = blockIdx.y;
    int tid = threadIdx.x;
    int lane = tid & 31, w = tid >> 5;

    __shared__ ABK s_abk;
    __shared__ int wtot[8];
    __shared__ int s_bin;
    __shared__ long long s_before, s_rankin;
    __shared__ int s_base, s_local;

    compute_abk(b, tid, &s_abk);
    if (tid == 0) { s_bin = -1; s_local = 0; }
    __syncthreads();
    long long r = s_abk.r;

    // level-0 selection scan over 8192 bins (32 per thread, two-pass, L1-hot)
    int mysum = 0;
    #pragma unroll 8
    for (int j = 0; j < 32; j++) mysum += (int)g_hcnt[b][tid*32+j];
    int incl = warp_scan_incl(mysum, lane);
    if (lane == 31) wtot[w] = incl;
    __syncthreads();
    int wbase = 0;
    #pragma unroll
    for (int j = 0; j < 8; j++) wbase += (j < w) ? wtot[j] : 0;
    long long base = (long long)wbase + incl - mysum;
    if (r >= 0 && r >= base && r < base + mysum) {
        long long cum = base;
        for (int j = 0; j < 32; j++) {
            unsigned cj = g_hcnt[b][tid*32+j];
            if (r < cum + (long long)cj) {
                s_bin = tid*32+j; s_before = cum; s_rankin = r - cum; break;
            }
            cum += (long long)cj;
        }
    }
    __syncthreads();

    int sel = s_bin;
    if (sel < 0) {                        // k == 0 case
        if (tid == 0 && blockIdx.x == 0) { g_sel0[b] = -1; g_k[b] = s_abk.k; }
        return;
    }
    unsigned selu = (unsigned)sel;

    int cnt = g_segcnt[b][blockIdx.x];
    const unsigned int* rb = g_resbits + (size_t)b * NMAX + (size_t)blockIdx.x * SEGLEN;

    // sweep 1: below-bin sum + match count (uint reads, no FMA)
    float sbelow = 0.f;
    int   cmatch = 0;
    for (int i = tid; i < cnt; i += TPB) {
        unsigned bits = rb[i];
        unsigned top = bits >> HSHIFT;
        if (top < selu) sbelow += __uint_as_float(bits);
        else if (top == selu) cmatch++;
    }
    float sb = warp_sum(sbelow);
    int   cm = warp_sum_i(cmatch);
    __shared__ float wsum[8];
    __shared__ int   wcm[8];
    if (lane == 0) { wsum[w] = sb; wcm[w] = cm; }
    __syncthreads();
    if (w == 0) {
        float a0 = lane < 8 ? wsum[lane] : 0.f;
        int   c0 = lane < 8 ? wcm[lane] : 0;
        a0 = warp_sum(a0); c0 = warp_sum_i(c0);
        if (lane == 0) {
            s_base = (c0 > 0) ? atomicAdd(&g_candcnt[b], c0) : 0;
            if (a0 != 0.f) atomicAdd(&g_sumbelow[b], (double)a0);
            if (blockIdx.x == 0) {
                g_sel0[b] = sel;
                g_k[b] = s_abk.k;
                g_rank[b] = s_rankin;
                g_cntbelow[b] = s_before;
            }
        }
    }
    __syncthreads();
    int cbase = s_base;
    unsigned int* cand = g_cand + (size_t)b * NMAX;

    // sweep 2 (segment L1-hot): write matches contiguously
    for (int i = tid; i < cnt; i += TPB) {
        unsigned bits = rb[i];
        if ((bits >> HSHIFT) == selu)
            cand[cbase + atomicAdd(&s_local, 1)] = bits;
    }
}

// ------------------------------ 4. finish ----------------------------------
#define FTPB 1024
__global__ __launch_bounds__(FTPB) void finish_kernel(float* __restrict__ out0) {
    int b = blockIdx.x;
    int tid = threadIdx.x;
    int lane = tid & 31, w = tid >> 5;
    int sel0 = g_sel0[b];
    int k = g_k[b];

    __shared__ unsigned int hist[1024];
    __shared__ int wtot[32];
    __shared__ int s_bin;
    __shared__ long long s_before;
    __shared__ double sred[32];
    __shared__ long long lred[32];

    if (sel0 < 0 || k <= 0) return;   // contributes 0 to the mean

    int m = g_candcnt[b];
    long long rw = g_rank[b];
    const unsigned int* cand = g_cand + (size_t)b * NMAX;

    // ---- pass A: bits[18:9], 1024 bins ----
    if (tid < 1024) hist[tid] = 0u;
    __syncthreads();
    for (int i = tid; i < m; i += FTPB)
        atomicAdd(&hist[(cand[i] >> 9) & 1023u], 1u);
    __syncthreads();
    {
        int mysum = (int)hist[tid];
        int incl = warp_scan_incl(mysum, lane);
        if (lane == 31) wtot[w] = incl;
        __syncthreads();
        int wbase = 0;
        for (int j = 0; j < w; j++) wbase += wtot[j];
        long long base = (long long)wbase + incl - mysum;
        if (rw >= base && rw < base + mysum) { s_bin = tid; s_before = base; }
        __syncthreads();
    }
    int selA = s_bin;
    rw -= s_before;
    __syncthreads();

    // ---- pass B: bits[8:0], 512 bins ----
    if (tid < 512) hist[tid] = 0u;
    __syncthreads();
    for (int i = tid; i < m; i += FTPB) {
        unsigned bits = cand[i];
        if (((bits >> 9) & 1023u) == (unsigned)selA)
            atomicAdd(&hist[bits & 511u], 1u);
    }
    __syncthreads();
    {
        int mysum = (tid < 512) ? (int)hist[tid] : 0;
        int incl = warp_scan_incl(mysum, lane);
        if (lane == 31) wtot[w] = incl;
        __syncthreads();
        int wbase = 0;
        for (int j = 0; j < w; j++) wbase += wtot[j];
        long long base = (long long)wbase + incl - mysum;
        if (tid < 512 && rw >= base && rw < base + mysum) s_bin = tid;
        __syncthreads();
    }
    int selB = s_bin;
    unsigned v_bits = ((unsigned)sel0 << HSHIFT) | ((unsigned)selA << 9) | (unsigned)selB;
    float v = __uint_as_float(v_bits);

    // ---- pass C: sum/count of candidates strictly below v ----
    double s = 0.0;
    long long c = 0;
    for (int i = tid; i < m; i += FTPB) {
        unsigned bits = cand[i];
        if (bits < v_bits) { s += (double)__uint_as_float(bits); c++; }
    }
    s = warp_sum_d(s);
    c = warp_sum_ll(c);
    if (lane == 0) { sred[w] = s; lred[w] = c; }
    __syncthreads();
    if (w == 0) {
        double sv = sred[lane];
        long long cv = lred[lane];
        sv = warp_sum_d(sv);
        cv = warp_sum_ll(cv);
        if (lane == 0) {
            long long total_less = g_cntbelow[b] + cv;
            double kept = g_sumbelow[b] + sv +
                          (double)((long long)k - total_less) * (double)v;
            float loss = (float)(kept / (double)k);
            atomicAdd(out0, loss / (float)BB);
        }
    }
}

// ------------------------------ launch -------------------------------------
extern "C" void kernel_launch(void* const* d_in, const int* in_sizes, int n_in,
                              void* d_out, int out_size) {
    const float* pred = (const float*)d_in[0];
    const float* gt   = (const float*)d_in[1];
    const int*   mask = (const int*)d_in[2];
    float* out = (float*)d_out;

    int total = in_sizes[0];
    int N = total / BB;

    dim3 grid(BLKX, BB);

    pack_kernel<<<grid, TPB>>>(pred, gt, mask, N, out);
    hist_kernel<<<grid, TPB>>>();
    compact_kernel<<<grid, TPB>>>();
    finish_kernel<<<BB, FTPB>>>(out);
}

// round 10
// speedup vs baseline: 1.6520x; 1.6520x over previous
#include <cuda_runtime.h>
#include <math.h>
#include <stdint.h>

// ---------------------------------------------------------------------------
// SSITrimLoss: masked scale/shift-invariant trimmed L1 loss.
// Pipeline (7 launches) — R5 structure (measured best) + ILP-4 finish:
//   1. pack      : moments + compact valid (p,g) pairs per block segment
//   2. finalize  : alpha/beta/k per sample; zero hists
//   3. hist      : res=|a*p+b-g| from pairs, 2048-bin count hist
//   4. select0   : pick level-0 bin + rank-within (hierarchical scan)
//   5. compact   : pairs again (L2-hot): below-bin sum/count + gather in-bin
//   6. finish    : per-sample 21-bit refine over candidates (4x unrolled MLP)
//   7. reduce    : mean over B -> out
// Selection is bit-exact (monotone uint encoding of non-negative floats).
// ---------------------------------------------------------------------------

#define BB    32
#define NMAX  491520
#define TPB   256
#define BLKX  32
#define SEGLEN (NMAX / BLKX)
#define FULLM 0xffffffffu

__device__ __align__(16) float2       g_pair[(size_t)BB * NMAX];
__device__ __align__(16) unsigned int g_cand[(size_t)BB * NMAX];
__device__ float              g_part[BB][BLKX][5];
__device__ int                g_segcnt[BB][BLKX];
__device__ unsigned int       g_hcnt[BB][2048];
__device__ float              g_alpha[BB], g_beta[BB];
__device__ int                g_k[BB];
__device__ long long          g_rank[BB];
__device__ int                g_sel0[BB];
__device__ double             g_sumbelow[BB];
__device__ unsigned long long g_cntbelow[BB];
__device__ int                g_candcnt[BB];
__device__ float              g_loss[BB];

// ------------------------- warp reduce/scan helpers ------------------------
__device__ __forceinline__ float warp_sum(float v) {
    #pragma unroll
    for (int off = 16; off; off >>= 1) v += __shfl_down_sync(FULLM, v, off);
    return v;
}
__device__ __forceinline__ double warp_sum_d(double v) {
    #pragma unroll
    for (int off = 16; off; off >>= 1) v += __shfl_down_sync(FULLM, v, off);
    return v;
}
__device__ __forceinline__ long long warp_sum_ll(long long v) {
    #pragma unroll
    for (int off = 16; off; off >>= 1) v += __shfl_down_sync(FULLM, v, off);
    return v;
}
__device__ __forceinline__ int warp_sum_i(int v) {
    #pragma unroll
    for (int off = 16; off; off >>= 1) v += __shfl_down_sync(FULLM, v, off);
    return v;
}
__device__ __forceinline__ int warp_scan_incl(int v, int lane) {
    #pragma unroll
    for (int off = 1; off < 32; off <<= 1) {
        int t = __shfl_up_sync(FULLM, v, off);
        if (lane >= off) v += t;
    }
    return v;
}

// ------------------------ 1. pack (moments + gather) -----------------------
__global__ __launch_bounds__(TPB) void pack_kernel(
        const float* __restrict__ pred, const float* __restrict__ gt,
        const int* __restrict__ mask, int N) {
    int b = blockIdx.y;
    int n4 = N >> 2;
    int chunk4 = n4 / BLKX;
    int start = blockIdx.x * chunk4;
    int end   = (blockIdx.x == BLKX - 1) ? n4 : start + chunk4;

    const float4* p4 = reinterpret_cast<const float4*>(pred) + (size_t)b * n4;
    const float4* g4 = reinterpret_cast<const float4*>(gt)   + (size_t)b * n4;
    const int4*   m4 = reinterpret_cast<const int4*>(mask)   + (size_t)b * n4;
    float2* out = g_pair + (size_t)b * NMAX + (size_t)blockIdx.x * SEGLEN;

    __shared__ int s_cnt;
    if (threadIdx.x == 0) s_cnt = 0;
    __syncthreads();

    int lane = threadIdx.x & 31;
    float sn = 0.f, sp = 0.f, sg = 0.f, spp = 0.f, spg = 0.f;

    for (int i = start + threadIdx.x; i < end; i += TPB) {
        float4 p = p4[i]; float4 g = g4[i]; int4 m = m4[i];
        bool v0 = m.x > 0, v1 = m.y > 0, v2 = m.z > 0, v3 = m.w > 0;
        if (v0) { sn += 1.f; sp += p.x; sg += g.x; spp += p.x*p.x; spg += p.x*g.x; }
        if (v1) { sn += 1.f; sp += p.y; sg += g.y; spp += p.y*p.y; spg += p.y*g.y; }
        if (v2) { sn += 1.f; sp += p.z; sg += g.z; spp += p.z*p.z; spg += p.z*g.z; }
        if (v3) { sn += 1.f; sp += p.w; sg += g.w; spp += p.w*p.w; spg += p.w*g.w; }
        int vc = (int)v0 + (int)v1 + (int)v2 + (int)v3;
        int incl = warp_scan_incl(vc, lane);
        int wtotal = __shfl_sync(FULLM, incl, 31);
        int base = 0;
        if (lane == 31 && wtotal) base = atomicAdd(&s_cnt, wtotal);
        base = __shfl_sync(FULLM, base, 31);
        int o = base + incl - vc;
        if (v0) out[o++] = make_float2(p.x, g.x);
        if (v1) out[o++] = make_float2(p.y, g.y);
        if (v2) out[o++] = make_float2(p.z, g.z);
        if (v3) out[o]   = make_float2(p.w, g.w);
    }

    sn = warp_sum(sn); sp = warp_sum(sp); sg = warp_sum(sg);
    spp = warp_sum(spp); spg = warp_sum(spg);
    __shared__ float ws[5][8];
    int w = threadIdx.x >> 5;
    if (lane == 0) { ws[0][w]=sn; ws[1][w]=sp; ws[2][w]=sg; ws[3][w]=spp; ws[4][w]=spg; }
    __syncthreads();
    if (w == 0) {
        float a0 = lane < 8 ? ws[0][lane] : 0.f;
        float a1 = lane < 8 ? ws[1][lane] : 0.f;
        float a2 = lane < 8 ? ws[2][lane] : 0.f;
        float a3 = lane < 8 ? ws[3][lane] : 0.f;
        float a4 = lane < 8 ? ws[4][lane] : 0.f;
        a0 = warp_sum(a0); a1 = warp_sum(a1); a2 = warp_sum(a2);
        a3 = warp_sum(a3); a4 = warp_sum(a4);
        if (lane == 0) {
            g_part[b][blockIdx.x][0] = a0;
            g_part[b][blockIdx.x][1] = a1;
            g_part[b][blockIdx.x][2] = a2;
            g_part[b][blockIdx.x][3] = a3;
            g_part[b][blockIdx.x][4] = a4;
            g_segcnt[b][blockIdx.x] = s_cnt;
        }
    }
}

// ------------------------------ 2. finalize --------------------------------
__global__ void finalize_kernel() {
    int b = blockIdx.x;
    int tid = threadIdx.x;
    for (int i = tid; i < 2048; i += blockDim.x) g_hcnt[b][i] = 0u;
    if (tid == 0) {
        g_candcnt[b] = 0;
        g_sumbelow[b] = 0.0;
        g_cntbelow[b] = 0ull;
    }
    if (tid < 32) {
        double v0 = (double)g_part[b][tid][0];
        double v1 = (double)g_part[b][tid][1];
        double v2 = (double)g_part[b][tid][2];
        double v3 = (double)g_part[b][tid][3];
        double v4 = (double)g_part[b][tid][4];
        v0 = warp_sum_d(v0); v1 = warp_sum_d(v1); v2 = warp_sum_d(v2);
        v3 = warp_sum_d(v3); v4 = warp_sum_d(v4);
        if (tid == 0) {
            double n  = v0;
            double ns = n < 1.0 ? 1.0 : n;
            double md = v1 / ns, mz = v2 / ns;
            double var = v3 / ns - md * md;
            double cov = v4 / ns - md * mz;
            double alpha = cov / (var + 1e-6);
            double beta  = mz - alpha * md;
            g_alpha[b] = (float)alpha;
            g_beta[b]  = (float)beta;
            int k = (int)floorf(0.8f * (float)n);   // reference-matching f32 arith
            g_k[b] = k;
            g_rank[b] = (long long)k - 1;
        }
    }
}

// ------------------------------ 3. hist ------------------------------------
__global__ __launch_bounds__(TPB) void hist_kernel(int N) {
    int b = blockIdx.y;
    __shared__ unsigned int sh[2048];
    for (int i = threadIdx.x; i < 2048; i += TPB) sh[i] = 0u;
    __syncthreads();

    int cnt = g_segcnt[b][blockIdx.x];
    const float2* in = g_pair + (size_t)b * NMAX + (size_t)blockIdx.x * SEGLEN;
    float a = g_alpha[b], be = g_beta[b];

    for (int i = threadIdx.x; i < cnt; i += TPB) {
        float2 pg = in[i];
        float r = fabsf(fmaf(a, pg.x, be) - pg.y);
        atomicAdd(&sh[__float_as_uint(r) >> 21], 1u);
    }
    __syncthreads();
    for (int i = threadIdx.x; i < 2048; i += TPB) {
        unsigned c = sh[i];
        if (c) atomicAdd(&g_hcnt[b][i], c);
    }
}

// ------------------------------ 4. select0 ---------------------------------
__global__ void select0_kernel() {
    int b = blockIdx.x;
    int tid = threadIdx.x;
    int lane = tid & 31, w = tid >> 5;
    long long r = g_rank[b];

    __shared__ int wtot[8];
    __shared__ int s_bin;
    __shared__ long long s_before;
    if (tid == 0) s_bin = -1;

    unsigned int c[8];
    int mysum = 0;
    #pragma unroll
    for (int j = 0; j < 8; j++) { c[j] = g_hcnt[b][tid*8+j]; mysum += (int)c[j]; }
    int incl = warp_scan_incl(mysum, lane);
    if (lane == 31) wtot[w] = incl;
    __syncthreads();
    int wbase = 0;
    #pragma unroll
    for (int j = 0; j < 8; j++) wbase += (j < w) ? wtot[j] : 0;
    long long base = (long long)wbase + incl - mysum;

    if (r >= base && r < base + mysum) {
        long long cum = base;
        #pragma unroll
        for (int j = 0; j < 8; j++) {
            if (r < cum + (long long)c[j]) { s_bin = tid*8+j; s_before = cum; break; }
            cum += (long long)c[j];
        }
    }
    __syncthreads();
    if (tid == 0) {
        if (s_bin >= 0) {
            g_sel0[b] = s_bin;
            g_rank[b] = r - s_before;
        } else {
            g_sel0[b] = -1;    // k == 0 case
        }
    }
}

// ------------------------------ 5. compact ---------------------------------
__global__ __launch_bounds__(TPB) void compact_kernel(int N) {
    int b = blockIdx.y;
    int cnt = g_segcnt[b][blockIdx.x];
    const float2* in = g_pair + (size_t)b * NMAX + (size_t)blockIdx.x * SEGLEN;
    unsigned int* cand = g_cand + (size_t)b * NMAX;
    float a = g_alpha[b], be = g_beta[b];
    unsigned selu = (unsigned)g_sel0[b];      // -1 -> huge, never matches

    float sbelow = 0.f;
    int   cbelow = 0, cmatch = 0;

    // pass 1: counts + below-bin sums
    for (int i = threadIdx.x; i < cnt; i += TPB) {
        float2 pg = in[i];
        float r = fabsf(fmaf(a, pg.x, be) - pg.y);
        unsigned top = __float_as_uint(r) >> 21;
        if (top < selu) { sbelow += r; cbelow++; }
        else if (top == selu) cmatch++;
    }

    __shared__ float wsum[8];
    __shared__ int   wcb[8], wcm[8];
    __shared__ int   s_base, s_local;
    int lane = threadIdx.x & 31, w = threadIdx.x >> 5;
    float sb = warp_sum(sbelow);
    int   cb = warp_sum_i(cbelow);
    int   cm = warp_sum_i(cmatch);
    if (lane == 0) { wsum[w] = sb; wcb[w] = cb; wcm[w] = cm; }
    __syncthreads();
    if (w == 0) {
        float a0 = lane < 8 ? wsum[lane] : 0.f;
        int   b0 = lane < 8 ? wcb[lane] : 0;
        int   c0 = lane < 8 ? wcm[lane] : 0;
        a0 = warp_sum(a0); b0 = warp_sum_i(b0); c0 = warp_sum_i(c0);
        if (lane == 0) {
            s_local = 0;
            s_base = (c0 > 0) ? atomicAdd(&g_candcnt[b], c0) : 0;
            if (b0 > 0) {
                atomicAdd(&g_sumbelow[b], (double)a0);
                atomicAdd(&g_cntbelow[b], (unsigned long long)b0);
            }
        }
    }
    __syncthreads();
    int base = s_base;

    // pass 2: gather in-bin candidates (segment is L1-hot from pass 1)
    for (int i = threadIdx.x; i < cnt; i += TPB) {
        float2 pg = in[i];
        float r = fabsf(fmaf(a, pg.x, be) - pg.y);
        unsigned bits = __float_as_uint(r);
        if ((bits >> 21) == selu) {
            int p = atomicAdd(&s_local, 1);
            cand[base + p] = bits;
        }
    }
}

// ------------------------------ 6. finish ----------------------------------
#define FTPB 1024
__global__ __launch_bounds__(FTPB) void finish_kernel() {
    int b = blockIdx.x;
    int tid = threadIdx.x;
    int lane = tid & 31, w = tid >> 5;
    int k = g_k[b];

    __shared__ unsigned int hist[2048];
    __shared__ int wtot[32];
    __shared__ int s_bin;
    __shared__ long long s_before;
    __shared__ double sred[32];
    __shared__ long long lred[32];

    if (k <= 0) { if (tid == 0) g_loss[b] = 0.f; return; }

    int m = g_candcnt[b];
    long long rw = g_rank[b];
    int sel0 = g_sel0[b];
    const unsigned int* cand = g_cand + (size_t)b * NMAX;

    // ---- pass A: bits[20:10], 2048 bins (4x unrolled loads for MLP) ----
    for (int i = tid; i < 2048; i += FTPB) hist[i] = 0u;
    __syncthreads();
    {
        int i = tid;
        for (; i + 3*FTPB < m; i += 4*FTPB) {
            unsigned b0 = cand[i];
            unsigned b1 = cand[i + FTPB];
            unsigned b2 = cand[i + 2*FTPB];
            unsigned b3 = cand[i + 3*FTPB];
            atomicAdd(&hist[(b0 >> 10) & 2047u], 1u);
            atomicAdd(&hist[(b1 >> 10) & 2047u], 1u);
            atomicAdd(&hist[(b2 >> 10) & 2047u], 1u);
            atomicAdd(&hist[(b3 >> 10) & 2047u], 1u);
        }
        for (; i < m; i += FTPB)
            atomicAdd(&hist[(cand[i] >> 10) & 2047u], 1u);
    }
    __syncthreads();
    {
        int c0 = (int)hist[tid*2], c1 = (int)hist[tid*2+1];
        int mysum = c0 + c1;
        int incl = warp_scan_incl(mysum, lane);
        if (lane == 31) wtot[w] = incl;
        __syncthreads();
        int wbase = 0;
        for (int j = 0; j < w; j++) wbase += wtot[j];
        long long base = (long long)wbase + incl - mysum;
        if (rw >= base && rw < base + mysum) {
            if (rw < base + c0) { s_bin = tid*2;   s_before = base; }
            else                { s_bin = tid*2+1; s_before = base + c0; }
        }
        __syncthreads();
    }
    int selA = s_bin;
    rw -= s_before;
    __syncthreads();

    // ---- pass B: bits[9:0], 1024 bins (4x unrolled) ----
    for (int i = tid; i < 1024; i += FTPB) hist[i] = 0u;
    __syncthreads();
    {
        unsigned selAu = (unsigned)selA;
        int i = tid;
        for (; i + 3*FTPB < m; i += 4*FTPB) {
            unsigned b0 = cand[i];
            unsigned b1 = cand[i + FTPB];
            unsigned b2 = cand[i + 2*FTPB];
            unsigned b3 = cand[i + 3*FTPB];
            if (((b0 >> 10) & 2047u) == selAu) atomicAdd(&hist[b0 & 1023u], 1u);
            if (((b1 >> 10) & 2047u) == selAu) atomicAdd(&hist[b1 & 1023u], 1u);
            if (((b2 >> 10) & 2047u) == selAu) atomicAdd(&hist[b2 & 1023u], 1u);
            if (((b3 >> 10) & 2047u) == selAu) atomicAdd(&hist[b3 & 1023u], 1u);
        }
        for (; i < m; i += FTPB) {
            unsigned bits = cand[i];
            if (((bits >> 10) & 2047u) == selAu)
                atomicAdd(&hist[bits & 1023u], 1u);
        }
    }
    __syncthreads();
    {
        int mysum = (int)hist[tid & 1023];
        int incl = warp_scan_incl(mysum, lane);
        if (lane == 31) wtot[w] = incl;
        __syncthreads();
        int wbase = 0;
        for (int j = 0; j < w; j++) wbase += wtot[j];
        long long base = (long long)wbase + incl - mysum;
        if (rw >= base && rw < base + mysum) s_bin = tid;
        __syncthreads();
    }
    int selB = s_bin;
    unsigned v_bits = ((unsigned)sel0 << 21) | ((unsigned)selA << 10) | (unsigned)selB;
    float v = __uint_as_float(v_bits);

    // ---- pass C: sum/count of candidates strictly below v (4x unrolled) ----
    double s = 0.0;
    long long c = 0;
    {
        int i = tid;
        for (; i + 3*FTPB < m; i += 4*FTPB) {
            unsigned b0 = cand[i];
            unsigned b1 = cand[i + FTPB];
            unsigned b2 = cand[i + 2*FTPB];
            unsigned b3 = cand[i + 3*FTPB];
            if (b0 < v_bits) { s += (double)__uint_as_float(b0); c++; }
            if (b1 < v_bits) { s += (double)__uint_as_float(b1); c++; }
            if (b2 < v_bits) { s += (double)__uint_as_float(b2); c++; }
            if (b3 < v_bits) { s += (double)__uint_as_float(b3); c++; }
        }
        for (; i < m; i += FTPB) {
            unsigned bits = cand[i];
            if (bits < v_bits) { s += (double)__uint_as_float(bits); c++; }
        }
    }
    s = warp_sum_d(s);
    c = warp_sum_ll(c);
    if (lane == 0) { sred[w] = s; lred[w] = c; }
    __syncthreads();
    if (w == 0) {
        double sv = sred[lane];
        long long cv = lred[lane];
        sv = warp_sum_d(sv);
        cv = warp_sum_ll(cv);
        if (lane == 0) {
            long long total_less = (long long)g_cntbelow[b] + cv;
            double kept = g_sumbelow[b] + sv +
                          (double)((long long)k - total_less) * (double)v;
            g_loss[b] = (float)(kept / (double)k);
        }
    }
}

// ------------------------------ 7. reduce ----------------------------------
__global__ void reduce_kernel(float* out) {
    int b = threadIdx.x;
    float loss = (b < BB) ? g_loss[b] : 0.f;
    #pragma unroll
    for (int off = 16; off; off >>= 1) loss += __shfl_down_sync(FULLM, loss, off);
    if (b == 0) out[0] = loss / (float)BB;
}

// ------------------------------ launch -------------------------------------
extern "C" void kernel_launch(void* const* d_in, const int* in_sizes, int n_in,
                              void* d_out, int out_size) {
    const float* pred = (const float*)d_in[0];
    const float* gt   = (const float*)d_in[1];
    const int*   mask = (const int*)d_in[2];
    float* out = (float*)d_out;

    int total = in_sizes[0];
    int N = total / BB;

    dim3 grid(BLKX, BB);

    pack_kernel<<<grid, TPB>>>(pred, gt, mask, N);
    finalize_kernel<<<BB, TPB>>>();
    hist_kernel<<<grid, TPB>>>(N);
    select0_kernel<<<BB, TPB>>>();
    compact_kernel<<<grid, TPB>>>(N);
    finish_kernel<<<BB, FTPB>>>();
    reduce_kernel<<<1, 32>>>(out);
}